// round 11
// baseline (speedup 1.0000x reference)
#include <cuda_runtime.h>
#include <cuda_bf16.h>

// Problem constants
#define BB      2
#define SS      2048
#define DIMM    1024
#define NHEADS  16
#define HDIM    64
#define WIN     256
#define NTOK    (BB*SS)          // 4096

typedef unsigned long long u64;
typedef unsigned int u32;

// Scratch (device globals: allocation-free)
__device__ __nv_bfloat16 g_qhi[NTOK * DIMM];
__device__ __nv_bfloat16 g_qlo[NTOK * DIMM];
__device__ __nv_bfloat16 g_khi[NTOK * DIMM];
__device__ __nv_bfloat16 g_klo[NTOK * DIMM];
__device__ __nv_bfloat16 g_vhi[NTOK * DIMM];
__device__ __nv_bfloat16 g_vlo[NTOK * DIMM];
__device__ __nv_bfloat16 gx_hi[NTOK * DIMM];
__device__ __nv_bfloat16 gx_lo[NTOK * DIMM];
__device__ __nv_bfloat16 gw_hi[3 * DIMM * DIMM];
__device__ __nv_bfloat16 gw_lo[3 * DIMM * DIMM];

// ---------------- helpers ----------------
__device__ __forceinline__ float ex2_approx(float x) {
    float r; asm("ex2.approx.f32 %0, %1;" : "=f"(r) : "f"(x)); return r;
}
__device__ __forceinline__ void ldsm4(u32& r0, u32& r1, u32& r2, u32& r3, u32 addr) {
    asm volatile("ldmatrix.sync.aligned.m8n8.x4.shared.b16 {%0,%1,%2,%3}, [%4];"
                 : "=r"(r0), "=r"(r1), "=r"(r2), "=r"(r3) : "r"(addr));
}
__device__ __forceinline__ void ldsm4t(u32& r0, u32& r1, u32& r2, u32& r3, u32 addr) {
    asm volatile("ldmatrix.sync.aligned.m8n8.x4.trans.shared.b16 {%0,%1,%2,%3}, [%4];"
                 : "=r"(r0), "=r"(r1), "=r"(r2), "=r"(r3) : "r"(addr));
}
__device__ __forceinline__ void mma_bf16(float* c, const u32* a, const u32* b) {
    asm volatile("mma.sync.aligned.m16n8k16.row.col.f32.bf16.bf16.f32 "
                 "{%0,%1,%2,%3}, {%4,%5,%6,%7}, {%8,%9}, {%0,%1,%2,%3};"
                 : "+f"(c[0]), "+f"(c[1]), "+f"(c[2]), "+f"(c[3])
                 : "r"(a[0]), "r"(a[1]), "r"(a[2]), "r"(a[3]), "r"(b[0]), "r"(b[1]));
}
__device__ __forceinline__ void cp16(u32 saddr, const void* gaddr) {
    asm volatile("cp.async.cg.shared.global [%0], [%1], 16;" :: "r"(saddr), "l"(gaddr));
}
__device__ __forceinline__ void cp_commit() { asm volatile("cp.async.commit_group;"); }
__device__ __forceinline__ void cp_wait1()  { asm volatile("cp.async.wait_group 1;"); }
__device__ __forceinline__ void cp_wait0()  { asm volatile("cp.async.wait_group 0;"); }
__device__ __forceinline__ u32 s2u(const void* p) { return (u32)__cvta_generic_to_shared(p); }
__device__ __forceinline__ u32 bf16x2(float hi, float lo) {
    u32 d; asm("cvt.rn.bf16x2.f32 %0, %1, %2;" : "=r"(d) : "f"(hi), "f"(lo)); return d;
}
__device__ __forceinline__ float bfr(float x) {
    return __bfloat162float(__float2bfloat16(x));
}

// ---------------- Kernel 0: fp32 -> bf16 hi/lo split ----------------
__global__ void split_bf16(const float* __restrict__ src,
                           __nv_bfloat16* __restrict__ hi,
                           __nv_bfloat16* __restrict__ lo, int n)
{
    int i = (blockIdx.x * blockDim.x + threadIdx.x) * 4;
    if (i >= n) return;
    float4 v = *(const float4*)(src + i);
    union { __nv_bfloat16 b[4]; uint2 u; } H, L;
    H.b[0] = __float2bfloat16(v.x); L.b[0] = __float2bfloat16(v.x - __bfloat162float(H.b[0]));
    H.b[1] = __float2bfloat16(v.y); L.b[1] = __float2bfloat16(v.y - __bfloat162float(H.b[1]));
    H.b[2] = __float2bfloat16(v.z); L.b[2] = __float2bfloat16(v.z - __bfloat162float(H.b[2]));
    H.b[3] = __float2bfloat16(v.w); L.b[3] = __float2bfloat16(v.w - __bfloat162float(H.b[3]));
    *(uint2*)(hi + i) = H.u;
    *(uint2*)(lo + i) = L.u;
}

// ---------------- Kernel 1: QKV GEMM on tensor cores (bf16 split) ----------------
#define RS 24   // smem row stride in bf16 (48B)

__global__ void __launch_bounds__(256) qkv_gemm_tc(
    const float* __restrict__ bq, const float* __restrict__ bk, const float* __restrict__ bv)
{
    __shared__ __align__(16) __nv_bfloat16 sm[2][4][128 * RS];  // 48KB

    const int z = blockIdx.z;
    const __nv_bfloat16* Ahg = gx_hi;
    const __nv_bfloat16* Alg = gx_lo;
    const __nv_bfloat16* Bhg = gw_hi + z * DIMM * DIMM;
    const __nv_bfloat16* Blg = gw_lo + z * DIMM * DIMM;
    __nv_bfloat16* Chi = (z == 0) ? g_qhi : (z == 1) ? g_khi : g_vhi;
    __nv_bfloat16* Clo = (z == 0) ? g_qlo : (z == 1) ? g_klo : g_vlo;
    const float* bias = (z == 0) ? bq : (z == 1) ? bk : bv;
    const float scale = (z == 0) ? (0.125f * 1.4426950408889634f) : 1.0f;

    const int row0 = blockIdx.y * 128;
    const int col0 = blockIdx.x * 128;
    const int tid  = threadIdx.x;
    const int wid  = tid >> 5;
    const int lane = tid & 31;
    const int wm   = (wid & 3) * 32;
    const int wn   = (wid >> 2) * 64;

    const int ldrow = tid >> 1;
    const int ldc   = tid & 1;
    const __nv_bfloat16* gA = Ahg + (size_t)(row0 + ldrow) * DIMM + ldc * 8;
    const __nv_bfloat16* gAl= Alg + (size_t)(row0 + ldrow) * DIMM + ldc * 8;
    const __nv_bfloat16* gB = Bhg + (size_t)(col0 + ldrow) * DIMM + ldc * 8;
    const __nv_bfloat16* gBl= Blg + (size_t)(col0 + ldrow) * DIMM + ldc * 8;
    const u32 soff = ldrow * RS + ldc * 8;

    float acc[2][8][4];
    #pragma unroll
    for (int mi = 0; mi < 2; mi++)
        #pragma unroll
        for (int ni = 0; ni < 8; ni++)
            #pragma unroll
            for (int e = 0; e < 4; e++) acc[mi][ni][e] = 0.0f;

    const int a_row = lane & 15, a_chk = lane >> 4;
    const int b_g = lane >> 3;
    const int b_row = (lane & 7) + ((b_g >> 1) << 3), b_chk = b_g & 1;

    cp16(s2u(&sm[0][0][soff]), gA);
    cp16(s2u(&sm[0][1][soff]), gAl);
    cp16(s2u(&sm[0][2][soff]), gB);
    cp16(s2u(&sm[0][3][soff]), gBl);
    cp_commit();

    #pragma unroll 1
    for (int it = 0; it < DIMM / 16; it++) {
        const int s = it & 1;
        if (it + 1 < DIMM / 16) {
            const int kt = (it + 1) * 16;
            cp16(s2u(&sm[s^1][0][soff]), gA  + kt);
            cp16(s2u(&sm[s^1][1][soff]), gAl + kt);
            cp16(s2u(&sm[s^1][2][soff]), gB  + kt);
            cp16(s2u(&sm[s^1][3][soff]), gBl + kt);
            cp_commit();
            cp_wait1();
        } else {
            cp_wait0();
        }
        __syncthreads();

        u32 ahi[2][4], alo[2][4], bhi[8][2], blo[8][2];
        #pragma unroll
        for (int mi = 0; mi < 2; mi++) {
            const int r = wm + mi * 16 + a_row;
            ldsm4(ahi[mi][0], ahi[mi][1], ahi[mi][2], ahi[mi][3], s2u(&sm[s][0][r * RS + a_chk * 8]));
            ldsm4(alo[mi][0], alo[mi][1], alo[mi][2], alo[mi][3], s2u(&sm[s][1][r * RS + a_chk * 8]));
        }
        #pragma unroll
        for (int p = 0; p < 4; p++) {
            const int r = wn + p * 16 + b_row;
            u32 r0, r1, r2, r3;
            ldsm4(r0, r1, r2, r3, s2u(&sm[s][2][r * RS + b_chk * 8]));
            bhi[2*p][0] = r0; bhi[2*p][1] = r1; bhi[2*p+1][0] = r2; bhi[2*p+1][1] = r3;
            ldsm4(r0, r1, r2, r3, s2u(&sm[s][3][r * RS + b_chk * 8]));
            blo[2*p][0] = r0; blo[2*p][1] = r1; blo[2*p+1][0] = r2; blo[2*p+1][1] = r3;
        }
        #pragma unroll
        for (int mi = 0; mi < 2; mi++)
            #pragma unroll
            for (int ni = 0; ni < 8; ni++) {
                mma_bf16(acc[mi][ni], ahi[mi], bhi[ni]);
                mma_bf16(acc[mi][ni], ahi[mi], blo[ni]);
                mma_bf16(acc[mi][ni], alo[mi], bhi[ni]);
            }
        __syncthreads();
    }

    const int crow = lane >> 2;
    const int ccol = (lane & 3) * 2;
    #pragma unroll
    for (int ni = 0; ni < 8; ni++) {
        const int n = col0 + wn + ni * 8 + ccol;
        const float b0 = bias[n], b1 = bias[n + 1];
        #pragma unroll
        for (int mi = 0; mi < 2; mi++) {
            #pragma unroll
            for (int half = 0; half < 2; half++) {
                const int m = row0 + wm + mi * 16 + crow + half * 8;
                float o0 = (acc[mi][ni][2*half]   + b0) * scale;
                float o1 = (acc[mi][ni][2*half+1] + b1) * scale;
                float h0 = bfr(o0), h1 = bfr(o1);
                size_t off = ((size_t)m * DIMM + n) >> 1;
                ((u32*)Chi)[off] = bf16x2(h1, h0);
                ((u32*)Clo)[off] = bf16x2(o1 - h1, o0 - h0);
            }
        }
    }
}

// ---------------- Kernel 2: flash attention on tensor cores ----------------
// Block = (b, h, 128-query tile); 8 warps x 16 rows; key tiles of 64.
// Double-buffered cp.async pipeline on K/V (2 stages x 4 arrays, dynamic smem 72KB).
// Mask: diagonal tiles d = j0-q0-WIN >= 0: banned iff col >= row-d.
#define LDK 72                 // smem row stride (144B) -> conflict-free ldmatrix
#define ASZ (64 * LDK)         // bf16 elems per tile array
#define ATTN_SMEM (2 * 4 * ASZ * 2)  // bytes = 73728

__global__ void __launch_bounds__(256) attn_mma(float* __restrict__ o_out)
{
    extern __shared__ __align__(16) __nv_bfloat16 smb[];   // [2][4][ASZ]

    const int b  = blockIdx.z;
    const int h  = blockIdx.y;
    const int qt = (int)gridDim.x - 1 - (int)blockIdx.x;   // heavy tiles first
    const int q0 = qt * 128;
    const int tid = threadIdx.x;
    const int wid = tid >> 5;
    const int lane = tid & 31;
    const int wm = wid * 16;                               // 0..112

    const int a_row = lane & 15, a_chk = lane >> 4;
    const int b_g = lane >> 3;
    const int b_row = (lane & 7) + ((b_g >> 1) << 3), b_chk = b_g & 1;

    __nv_bfloat16* buf[8];
    #pragma unroll
    for (int i = 0; i < 8; i++) buf[i] = smb + i * ASZ;
    // stage st arrays: kh=buf[st*4+0], kl=buf[st*4+1], vh=buf[st*4+2], vl=buf[st*4+3]

    // ---- stage Q (128 rows hi+lo) through stage-0 buffers, extract A-frags ----
    u32 qh[4][4], ql[4][4];
    {
        const __nv_bfloat16* gq  = g_qhi + (size_t)(b * SS + q0) * DIMM + h * HDIM;
        const __nv_bfloat16* gql = g_qlo + (size_t)(b * SS + q0) * DIMM + h * HDIM;
        #pragma unroll
        for (int u = 0; u < 8; u++) {
            int c = tid + u * 256;            // 0..2047 chunks of 16B
            int arr = c >> 9;                 // 0: hi r0-63, 1: hi r64-127, 2: lo r0-63, 3: lo r64-127
            int idx = c & 511;
            int row = idx >> 3, cc = idx & 7;
            int grow = row + (arr & 1) * 64;
            const __nv_bfloat16* src = (arr < 2) ? gq : gql;
            cp16(s2u(&buf[arr][row * LDK + cc * 8]), src + (size_t)grow * DIMM + cc * 8);
        }
        cp_commit(); cp_wait0(); __syncthreads();
        __nv_bfloat16* bh = buf[(wm >> 6) & 1];        // hi buffer for this warp
        __nv_bfloat16* bl = buf[2 + ((wm >> 6) & 1)];  // lo buffer
        const int r = (wm & 63) + a_row;
        #pragma unroll
        for (int kk = 0; kk < 4; kk++) {
            ldsm4(qh[kk][0], qh[kk][1], qh[kk][2], qh[kk][3], s2u(&bh[r * LDK + kk * 16 + a_chk * 8]));
            ldsm4(ql[kk][0], ql[kk][1], ql[kk][2], ql[kk][3], s2u(&bl[r * LDK + kk * 16 + a_chk * 8]));
        }
        __syncthreads();
    }

    float outf[8][4];
    #pragma unroll
    for (int ni = 0; ni < 8; ni++)
        #pragma unroll
        for (int e = 0; e < 4; e++) outf[ni][e] = 0.0f;
    float m0 = -1e30f, m1 = -1e30f, l0 = 0.0f, l1 = 0.0f;

    const int jend  = min(SS, q0 + 127 + WIN);
    const int ntile = (jend + 63) >> 6;
    const __nv_bfloat16* Kh = g_khi + (size_t)(b * SS) * DIMM + h * HDIM;
    const __nv_bfloat16* Kl = g_klo + (size_t)(b * SS) * DIMM + h * HDIM;
    const __nv_bfloat16* Vh = g_vhi + (size_t)(b * SS) * DIMM + h * HDIM;
    const __nv_bfloat16* Vl = g_vlo + (size_t)(b * SS) * DIMM + h * HDIM;

    // prologue: load tile 0 into stage 0
    {
        #pragma unroll
        for (int u = 0; u < 8; u++) {
            int c = tid + u * 256;
            int arr = c >> 9, idx = c & 511;
            int row = idx >> 3, cc = idx & 7;
            const __nv_bfloat16* src = (arr == 0) ? Kh : (arr == 1) ? Kl : (arr == 2) ? Vh : Vl;
            cp16(s2u(&buf[arr][row * LDK + cc * 8]), src + (size_t)row * DIMM + cc * 8);
        }
        cp_commit();
    }

    #pragma unroll 1
    for (int it = 0; it < ntile; it++) {
        const int st = it & 1;
        const int j0 = it * 64;
        if (it + 1 < ntile) {
            const int jn = (it + 1) * 64;
            #pragma unroll
            for (int u = 0; u < 8; u++) {
                int c = tid + u * 256;
                int arr = c >> 9, idx = c & 511;
                int row = idx >> 3, cc = idx & 7;
                const __nv_bfloat16* src = (arr == 0) ? Kh : (arr == 1) ? Kl : (arr == 2) ? Vh : Vl;
                cp16(s2u(&buf[(st^1)*4 + arr][row * LDK + cc * 8]), src + (size_t)(jn + row) * DIMM + cc * 8);
            }
            cp_commit();
            cp_wait1();
        } else {
            cp_wait0();
        }
        __syncthreads();

        __nv_bfloat16* skh = buf[st*4 + 0];
        __nv_bfloat16* skl = buf[st*4 + 1];
        __nv_bfloat16* svh = buf[st*4 + 2];
        __nv_bfloat16* svl = buf[st*4 + 3];

        // ---- S = Q K^T (3-pass split) ----
        float s[8][4];
        #pragma unroll
        for (int ni = 0; ni < 8; ni++)
            #pragma unroll
            for (int e = 0; e < 4; e++) s[ni][e] = 0.0f;

        #pragma unroll
        for (int pj = 0; pj < 4; pj++) {
            #pragma unroll
            for (int kk = 0; kk < 4; kk++) {
                u32 h0, h1, h2, h3, lo0, lo1, lo2, lo3;
                ldsm4(h0, h1, h2, h3,     s2u(&skh[(pj * 16 + b_row) * LDK + kk * 16 + b_chk * 8]));
                ldsm4(lo0, lo1, lo2, lo3, s2u(&skl[(pj * 16 + b_row) * LDK + kk * 16 + b_chk * 8]));
                u32 Bh0[2] = {h0, h1}, Bh1[2] = {h2, h3};
                u32 Bl0[2] = {lo0, lo1}, Bl1[2] = {lo2, lo3};
                mma_bf16(s[2*pj],   qh[kk], Bh0);
                mma_bf16(s[2*pj],   qh[kk], Bl0);
                mma_bf16(s[2*pj],   ql[kk], Bh0);
                mma_bf16(s[2*pj+1], qh[kk], Bh1);
                mma_bf16(s[2*pj+1], qh[kk], Bl1);
                mma_bf16(s[2*pj+1], ql[kk], Bh1);
            }
        }

        // ---- diagonal masking: banned iff col >= row - d, d = j0-q0-WIN ----
        const int d = j0 - q0 - WIN;
        if (d >= 0) {
            const int r0 = wm + (lane >> 2);
            const int c0 = (lane & 3) * 2;
            #pragma unroll
            for (int ni = 0; ni < 8; ni++) {
                int col = ni * 8 + c0;
                if (col     >= r0 - d)     s[ni][0] = -1e30f;
                if (col + 1 >= r0 - d)     s[ni][1] = -1e30f;
                if (col     >= r0 + 8 - d) s[ni][2] = -1e30f;
                if (col + 1 >= r0 + 8 - d) s[ni][3] = -1e30f;
            }
        }

        // ---- online softmax (base 2) ----
        float mx0 = -1e30f, mx1 = -1e30f;
        #pragma unroll
        for (int ni = 0; ni < 8; ni++) {
            mx0 = fmaxf(mx0, fmaxf(s[ni][0], s[ni][1]));
            mx1 = fmaxf(mx1, fmaxf(s[ni][2], s[ni][3]));
        }
        mx0 = fmaxf(mx0, __shfl_xor_sync(0xffffffffu, mx0, 1));
        mx0 = fmaxf(mx0, __shfl_xor_sync(0xffffffffu, mx0, 2));
        mx1 = fmaxf(mx1, __shfl_xor_sync(0xffffffffu, mx1, 1));
        mx1 = fmaxf(mx1, __shfl_xor_sync(0xffffffffu, mx1, 2));
        float nm0 = fmaxf(m0, mx0), nm1 = fmaxf(m1, mx1);
        float cr0 = ex2_approx(m0 - nm0), cr1 = ex2_approx(m1 - nm1);
        m0 = nm0; m1 = nm1; l0 *= cr0; l1 *= cr1;
        #pragma unroll
        for (int ni = 0; ni < 8; ni++) {
            outf[ni][0] *= cr0; outf[ni][1] *= cr0;
            outf[ni][2] *= cr1; outf[ni][3] *= cr1;
        }
        #pragma unroll
        for (int ni = 0; ni < 8; ni++) {
            s[ni][0] = ex2_approx(s[ni][0] - m0);
            s[ni][1] = ex2_approx(s[ni][1] - m0);
            s[ni][2] = ex2_approx(s[ni][2] - m1);
            s[ni][3] = ex2_approx(s[ni][3] - m1);
            l0 += s[ni][0] + s[ni][1];
            l1 += s[ni][2] + s[ni][3];
        }

        // ---- P V (3-pass split) ----
        #pragma unroll
        for (int kk = 0; kk < 4; kk++) {
            float p00 = s[2*kk][0],   p01 = s[2*kk][1],   p02 = s[2*kk][2],   p03 = s[2*kk][3];
            float p10 = s[2*kk+1][0], p11 = s[2*kk+1][1], p12 = s[2*kk+1][2], p13 = s[2*kk+1][3];
            float h00 = bfr(p00), h01 = bfr(p01), h02 = bfr(p02), h03 = bfr(p03);
            float h10 = bfr(p10), h11 = bfr(p11), h12 = bfr(p12), h13 = bfr(p13);
            u32 ph[4] = { bf16x2(h01, h00), bf16x2(h03, h02), bf16x2(h11, h10), bf16x2(h13, h12) };
            u32 pl[4] = { bf16x2(p01 - h01, p00 - h00), bf16x2(p03 - h03, p02 - h02),
                          bf16x2(p11 - h11, p10 - h10), bf16x2(p13 - h13, p12 - h12) };
            #pragma unroll
            for (int pd = 0; pd < 4; pd++) {
                u32 v0, v1, v2, v3, w0, w1, w2, w3;
                ldsm4t(v0, v1, v2, v3, s2u(&svh[(kk * 16 + a_row) * LDK + pd * 16 + a_chk * 8]));
                ldsm4t(w0, w1, w2, w3, s2u(&svl[(kk * 16 + a_row) * LDK + pd * 16 + a_chk * 8]));
                u32 Vh0[2] = {v0, v1}, Vh1[2] = {v2, v3};
                u32 Vl0[2] = {w0, w1}, Vl1[2] = {w2, w3};
                mma_bf16(outf[2*pd],   ph, Vh0);
                mma_bf16(outf[2*pd],   ph, Vl0);
                mma_bf16(outf[2*pd],   pl, Vh0);
                mma_bf16(outf[2*pd+1], ph, Vh1);
                mma_bf16(outf[2*pd+1], ph, Vl1);
                mma_bf16(outf[2*pd+1], pl, Vh1);
            }
        }
        __syncthreads();
    }

    // ---- finalize ----
    l0 += __shfl_xor_sync(0xffffffffu, l0, 1);
    l0 += __shfl_xor_sync(0xffffffffu, l0, 2);
    l1 += __shfl_xor_sync(0xffffffffu, l1, 1);
    l1 += __shfl_xor_sync(0xffffffffu, l1, 2);
    const float i0 = 1.0f / l0, i1 = 1.0f / l1;

    const int r0 = q0 + wm + (lane >> 2);
    const int c0 = (lane & 3) * 2;
    #pragma unroll
    for (int nd = 0; nd < 8; nd++) {
        const int d2 = nd * 8 + c0;
        float* p0 = o_out + (size_t)(b * SS + r0) * DIMM + h * HDIM + d2;
        p0[0] = outf[nd][0] * i0;
        p0[1] = outf[nd][1] * i0;
        float* p1 = o_out + (size_t)(b * SS + r0 + 8) * DIMM + h * HDIM + d2;
        p1[0] = outf[nd][2] * i1;
        p1[1] = outf[nd][3] * i1;
    }
}

// ---------------- launch ----------------
extern "C" void kernel_launch(void* const* d_in, const int* in_sizes, int n_in,
                              void* d_out, int out_size)
{
    const float* x  = (const float*)d_in[0];
    const float* Wq = (const float*)d_in[1];
    const float* bq = (const float*)d_in[2];
    const float* Wk = (const float*)d_in[3];
    const float* bk = (const float*)d_in[4];
    const float* Wv = (const float*)d_in[5];
    const float* bv = (const float*)d_in[6];
    float* out = (float*)d_out;

    __nv_bfloat16 *xhi, *xlo, *whi, *wlo;
    cudaGetSymbolAddress((void**)&xhi, gx_hi);
    cudaGetSymbolAddress((void**)&xlo, gx_lo);
    cudaGetSymbolAddress((void**)&whi, gw_hi);
    cudaGetSymbolAddress((void**)&wlo, gw_lo);

    split_bf16<<<(NTOK * DIMM) / 1024, 256>>>(x, xhi, xlo, NTOK * DIMM);
    split_bf16<<<(DIMM * DIMM) / 1024, 256>>>(Wq, whi, wlo, DIMM * DIMM);
    split_bf16<<<(DIMM * DIMM) / 1024, 256>>>(Wk, whi + DIMM * DIMM, wlo + DIMM * DIMM, DIMM * DIMM);
    split_bf16<<<(DIMM * DIMM) / 1024, 256>>>(Wv, whi + 2 * DIMM * DIMM, wlo + 2 * DIMM * DIMM, DIMM * DIMM);

    dim3 ggrid(DIMM / 128, NTOK / 128, 3);
    qkv_gemm_tc<<<ggrid, 256>>>(bq, bk, bv);

    // idempotent, deterministic (no static guard — harness rule)
    cudaFuncSetAttribute(attn_mma, cudaFuncAttributeMaxDynamicSharedMemorySize, ATTN_SMEM);
    dim3 agrid(SS / 128, NHEADS, BB);   // 16 x 16 x 2 = 512 blocks
    attn_mma<<<agrid, 256, ATTN_SMEM>>>(out);
}

// round 12
// speedup vs baseline: 1.0530x; 1.0530x over previous
#include <cuda_runtime.h>
#include <cuda_bf16.h>

// Problem constants
#define BB      2
#define SS      2048
#define DIMM    1024
#define NHEADS  16
#define HDIM    64
#define WIN     256
#define NTOK    (BB*SS)          // 4096

typedef unsigned long long u64;
typedef unsigned int u32;

// Scratch (device globals: allocation-free)
__device__ __nv_bfloat16 g_qhi[NTOK * DIMM];
__device__ __nv_bfloat16 g_qlo[NTOK * DIMM];
__device__ __nv_bfloat16 g_khi[NTOK * DIMM];
__device__ __nv_bfloat16 g_klo[NTOK * DIMM];
__device__ __nv_bfloat16 g_vhi[NTOK * DIMM];
__device__ __nv_bfloat16 g_vlo[NTOK * DIMM];
__device__ __nv_bfloat16 gx_hi[NTOK * DIMM];
__device__ __nv_bfloat16 gx_lo[NTOK * DIMM];
__device__ __nv_bfloat16 gw_hi[3 * DIMM * DIMM];
__device__ __nv_bfloat16 gw_lo[3 * DIMM * DIMM];

// ---------------- helpers ----------------
__device__ __forceinline__ float ex2_approx(float x) {
    float r; asm("ex2.approx.f32 %0, %1;" : "=f"(r) : "f"(x)); return r;
}
__device__ __forceinline__ void ldsm4(u32& r0, u32& r1, u32& r2, u32& r3, u32 addr) {
    asm volatile("ldmatrix.sync.aligned.m8n8.x4.shared.b16 {%0,%1,%2,%3}, [%4];"
                 : "=r"(r0), "=r"(r1), "=r"(r2), "=r"(r3) : "r"(addr));
}
__device__ __forceinline__ void ldsm4t(u32& r0, u32& r1, u32& r2, u32& r3, u32 addr) {
    asm volatile("ldmatrix.sync.aligned.m8n8.x4.trans.shared.b16 {%0,%1,%2,%3}, [%4];"
                 : "=r"(r0), "=r"(r1), "=r"(r2), "=r"(r3) : "r"(addr));
}
__device__ __forceinline__ void mma_bf16(float* c, const u32* a, const u32* b) {
    asm volatile("mma.sync.aligned.m16n8k16.row.col.f32.bf16.bf16.f32 "
                 "{%0,%1,%2,%3}, {%4,%5,%6,%7}, {%8,%9}, {%0,%1,%2,%3};"
                 : "+f"(c[0]), "+f"(c[1]), "+f"(c[2]), "+f"(c[3])
                 : "r"(a[0]), "r"(a[1]), "r"(a[2]), "r"(a[3]), "r"(b[0]), "r"(b[1]));
}
__device__ __forceinline__ void cp16(u32 saddr, const void* gaddr) {
    asm volatile("cp.async.cg.shared.global [%0], [%1], 16;" :: "r"(saddr), "l"(gaddr));
}
__device__ __forceinline__ void cp_commit() { asm volatile("cp.async.commit_group;"); }
__device__ __forceinline__ void cp_wait1()  { asm volatile("cp.async.wait_group 1;"); }
__device__ __forceinline__ void cp_wait0()  { asm volatile("cp.async.wait_group 0;"); }
__device__ __forceinline__ u32 s2u(const void* p) { return (u32)__cvta_generic_to_shared(p); }
__device__ __forceinline__ u32 bf16x2(float hi, float lo) {
    u32 d; asm("cvt.rn.bf16x2.f32 %0, %1, %2;" : "=r"(d) : "f"(hi), "f"(lo)); return d;
}
__device__ __forceinline__ float bfr(float x) {
    return __bfloat162float(__float2bfloat16(x));
}

// ---------------- Kernel 0: fp32 -> bf16 hi/lo split ----------------
__global__ void split_bf16(const float* __restrict__ src,
                           __nv_bfloat16* __restrict__ hi,
                           __nv_bfloat16* __restrict__ lo, int n)
{
    int i = (blockIdx.x * blockDim.x + threadIdx.x) * 4;
    if (i >= n) return;
    float4 v = *(const float4*)(src + i);
    union { __nv_bfloat16 b[4]; uint2 u; } H, L;
    H.b[0] = __float2bfloat16(v.x); L.b[0] = __float2bfloat16(v.x - __bfloat162float(H.b[0]));
    H.b[1] = __float2bfloat16(v.y); L.b[1] = __float2bfloat16(v.y - __bfloat162float(H.b[1]));
    H.b[2] = __float2bfloat16(v.z); L.b[2] = __float2bfloat16(v.z - __bfloat162float(H.b[2]));
    H.b[3] = __float2bfloat16(v.w); L.b[3] = __float2bfloat16(v.w - __bfloat162float(H.b[3]));
    *(uint2*)(hi + i) = H.u;
    *(uint2*)(lo + i) = L.u;
}

// ---------------- Kernel 1: QKV GEMM on tensor cores (bf16 split) ----------------
#define RS 24   // smem row stride in bf16 (48B)

__global__ void __launch_bounds__(256) qkv_gemm_tc(
    const float* __restrict__ bq, const float* __restrict__ bk, const float* __restrict__ bv)
{
    __shared__ __align__(16) __nv_bfloat16 sm[2][4][128 * RS];  // 48KB

    const int z = blockIdx.z;
    const __nv_bfloat16* Ahg = gx_hi;
    const __nv_bfloat16* Alg = gx_lo;
    const __nv_bfloat16* Bhg = gw_hi + z * DIMM * DIMM;
    const __nv_bfloat16* Blg = gw_lo + z * DIMM * DIMM;
    __nv_bfloat16* Chi = (z == 0) ? g_qhi : (z == 1) ? g_khi : g_vhi;
    __nv_bfloat16* Clo = (z == 0) ? g_qlo : (z == 1) ? g_klo : g_vlo;
    const float* bias = (z == 0) ? bq : (z == 1) ? bk : bv;
    const float scale = (z == 0) ? (0.125f * 1.4426950408889634f) : 1.0f;

    const int row0 = blockIdx.y * 128;
    const int col0 = blockIdx.x * 128;
    const int tid  = threadIdx.x;
    const int wid  = tid >> 5;
    const int lane = tid & 31;
    const int wm   = (wid & 3) * 32;
    const int wn   = (wid >> 2) * 64;

    const int ldrow = tid >> 1;
    const int ldc   = tid & 1;
    const __nv_bfloat16* gA = Ahg + (size_t)(row0 + ldrow) * DIMM + ldc * 8;
    const __nv_bfloat16* gAl= Alg + (size_t)(row0 + ldrow) * DIMM + ldc * 8;
    const __nv_bfloat16* gB = Bhg + (size_t)(col0 + ldrow) * DIMM + ldc * 8;
    const __nv_bfloat16* gBl= Blg + (size_t)(col0 + ldrow) * DIMM + ldc * 8;
    const u32 soff = ldrow * RS + ldc * 8;

    float acc[2][8][4];
    #pragma unroll
    for (int mi = 0; mi < 2; mi++)
        #pragma unroll
        for (int ni = 0; ni < 8; ni++)
            #pragma unroll
            for (int e = 0; e < 4; e++) acc[mi][ni][e] = 0.0f;

    const int a_row = lane & 15, a_chk = lane >> 4;
    const int b_g = lane >> 3;
    const int b_row = (lane & 7) + ((b_g >> 1) << 3), b_chk = b_g & 1;

    cp16(s2u(&sm[0][0][soff]), gA);
    cp16(s2u(&sm[0][1][soff]), gAl);
    cp16(s2u(&sm[0][2][soff]), gB);
    cp16(s2u(&sm[0][3][soff]), gBl);
    cp_commit();

    #pragma unroll 1
    for (int it = 0; it < DIMM / 16; it++) {
        const int s = it & 1;
        if (it + 1 < DIMM / 16) {
            const int kt = (it + 1) * 16;
            cp16(s2u(&sm[s^1][0][soff]), gA  + kt);
            cp16(s2u(&sm[s^1][1][soff]), gAl + kt);
            cp16(s2u(&sm[s^1][2][soff]), gB  + kt);
            cp16(s2u(&sm[s^1][3][soff]), gBl + kt);
            cp_commit();
            cp_wait1();
        } else {
            cp_wait0();
        }
        __syncthreads();

        u32 ahi[2][4], alo[2][4], bhi[8][2], blo[8][2];
        #pragma unroll
        for (int mi = 0; mi < 2; mi++) {
            const int r = wm + mi * 16 + a_row;
            ldsm4(ahi[mi][0], ahi[mi][1], ahi[mi][2], ahi[mi][3], s2u(&sm[s][0][r * RS + a_chk * 8]));
            ldsm4(alo[mi][0], alo[mi][1], alo[mi][2], alo[mi][3], s2u(&sm[s][1][r * RS + a_chk * 8]));
        }
        #pragma unroll
        for (int p = 0; p < 4; p++) {
            const int r = wn + p * 16 + b_row;
            u32 r0, r1, r2, r3;
            ldsm4(r0, r1, r2, r3, s2u(&sm[s][2][r * RS + b_chk * 8]));
            bhi[2*p][0] = r0; bhi[2*p][1] = r1; bhi[2*p+1][0] = r2; bhi[2*p+1][1] = r3;
            ldsm4(r0, r1, r2, r3, s2u(&sm[s][3][r * RS + b_chk * 8]));
            blo[2*p][0] = r0; blo[2*p][1] = r1; blo[2*p+1][0] = r2; blo[2*p+1][1] = r3;
        }
        #pragma unroll
        for (int mi = 0; mi < 2; mi++)
            #pragma unroll
            for (int ni = 0; ni < 8; ni++) {
                mma_bf16(acc[mi][ni], ahi[mi], bhi[ni]);
                mma_bf16(acc[mi][ni], ahi[mi], blo[ni]);
                mma_bf16(acc[mi][ni], alo[mi], bhi[ni]);
            }
        __syncthreads();
    }

    const int crow = lane >> 2;
    const int ccol = (lane & 3) * 2;
    #pragma unroll
    for (int ni = 0; ni < 8; ni++) {
        const int n = col0 + wn + ni * 8 + ccol;
        const float b0 = bias[n], b1 = bias[n + 1];
        #pragma unroll
        for (int mi = 0; mi < 2; mi++) {
            #pragma unroll
            for (int half = 0; half < 2; half++) {
                const int m = row0 + wm + mi * 16 + crow + half * 8;
                float o0 = (acc[mi][ni][2*half]   + b0) * scale;
                float o1 = (acc[mi][ni][2*half+1] + b1) * scale;
                float h0 = bfr(o0), h1 = bfr(o1);
                size_t off = ((size_t)m * DIMM + n) >> 1;
                ((u32*)Chi)[off] = bf16x2(h1, h0);
                ((u32*)Clo)[off] = bf16x2(o1 - h1, o0 - h0);
            }
        }
    }
}

// ---------------- Kernel 2: flash attention on tensor cores ----------------
// Block = (b, h, 64-query tile); 4 warps x 16 rows; key tiles of 64.
// 36KB static smem -> high occupancy (cross-block overlap hides K latency).
// K and V are separate cp.async groups: V load overlaps S mma + softmax.
#define LDK 72   // smem row stride in bf16 (144B) -> conflict-free ldmatrix

__global__ void __launch_bounds__(128) attn_mma(float* __restrict__ o_out)
{
    __shared__ __align__(16) __nv_bfloat16 skh[64 * LDK], skl[64 * LDK];
    __shared__ __align__(16) __nv_bfloat16 svh[64 * LDK], svl[64 * LDK];

    const int b  = blockIdx.z;
    const int h  = blockIdx.y;
    const int qt = (int)gridDim.x - 1 - (int)blockIdx.x;  // heavy tiles first
    const int q0 = qt * 64;
    const int tid = threadIdx.x;
    const int wid = tid >> 5;
    const int lane = tid & 31;
    const int wm = wid * 16;

    const int a_row = lane & 15, a_chk = lane >> 4;
    const int b_g = lane >> 3;
    const int b_row = (lane & 7) + ((b_g >> 1) << 3), b_chk = b_g & 1;

    // ---- load Q A-fragments (via smem staging in skh/skl) ----
    u32 qh[4][4], ql[4][4];
    {
        const __nv_bfloat16* gq  = g_qhi + (size_t)(b * SS + q0) * DIMM + h * HDIM;
        const __nv_bfloat16* gql = g_qlo + (size_t)(b * SS + q0) * DIMM + h * HDIM;
        #pragma unroll
        for (int u = 0; u < 4; u++) {
            int c = tid + u * 128;       // 512 chunks per array
            int row = c >> 3, cc = c & 7;
            cp16(s2u(&skh[row * LDK + cc * 8]), gq  + (size_t)row * DIMM + cc * 8);
            cp16(s2u(&skl[row * LDK + cc * 8]), gql + (size_t)row * DIMM + cc * 8);
        }
        cp_commit(); cp_wait0(); __syncthreads();
        #pragma unroll
        for (int kk = 0; kk < 4; kk++) {
            ldsm4(qh[kk][0], qh[kk][1], qh[kk][2], qh[kk][3],
                  s2u(&skh[(wm + a_row) * LDK + kk * 16 + a_chk * 8]));
            ldsm4(ql[kk][0], ql[kk][1], ql[kk][2], ql[kk][3],
                  s2u(&skl[(wm + a_row) * LDK + kk * 16 + a_chk * 8]));
        }
        __syncthreads();
    }

    float outf[8][4];
    #pragma unroll
    for (int ni = 0; ni < 8; ni++)
        #pragma unroll
        for (int e = 0; e < 4; e++) outf[ni][e] = 0.0f;
    float m0 = -1e30f, m1 = -1e30f, l0 = 0.0f, l1 = 0.0f;

    const int jend = min(SS, q0 + 63 + WIN);
    const __nv_bfloat16* Kh = g_khi + (size_t)(b * SS) * DIMM + h * HDIM;
    const __nv_bfloat16* Kl = g_klo + (size_t)(b * SS) * DIMM + h * HDIM;
    const __nv_bfloat16* Vh = g_vhi + (size_t)(b * SS) * DIMM + h * HDIM;
    const __nv_bfloat16* Vl = g_vlo + (size_t)(b * SS) * DIMM + h * HDIM;

    #pragma unroll 1
    for (int j0 = 0; j0 < jend; j0 += 64) {
        // ---- group 1: K hi/lo (chunks 0..1023) ----
        #pragma unroll
        for (int u = 0; u < 8; u++) {
            int c = tid + u * 128;               // 0..1023
            int arr = c >> 9, idx = c & 511;     // arr 0,1
            int row = idx >> 3, cc = idx & 7;
            size_t g = (size_t)(j0 + row) * DIMM + cc * 8;
            u32 d = (u32)(row * LDK + cc * 8);
            if (arr == 0) cp16(s2u(&skh[d]), Kh + g);
            else          cp16(s2u(&skl[d]), Kl + g);
        }
        cp_commit();
        // ---- group 2: V hi/lo (chunks 1024..2047) ----
        #pragma unroll
        for (int u = 8; u < 16; u++) {
            int c = tid + u * 128;
            int arr = (c >> 9) & 1, idx = c & 511;  // arr 0 -> vh, 1 -> vl
            int row = idx >> 3, cc = idx & 7;
            size_t g = (size_t)(j0 + row) * DIMM + cc * 8;
            u32 d = (u32)(row * LDK + cc * 8);
            if (arr == 0) cp16(s2u(&svh[d]), Vh + g);
            else          cp16(s2u(&svl[d]), Vl + g);
        }
        cp_commit();

        cp_wait1();            // K ready; V still in flight
        __syncthreads();

        // ---- S = Q K^T (3-pass split) ----
        float s[8][4];
        #pragma unroll
        for (int ni = 0; ni < 8; ni++)
            #pragma unroll
            for (int e = 0; e < 4; e++) s[ni][e] = 0.0f;

        #pragma unroll
        for (int pj = 0; pj < 4; pj++) {
            #pragma unroll
            for (int kk = 0; kk < 4; kk++) {
                u32 h0, h1, h2, h3, lo0, lo1, lo2, lo3;
                ldsm4(h0, h1, h2, h3,     s2u(&skh[(pj * 16 + b_row) * LDK + kk * 16 + b_chk * 8]));
                ldsm4(lo0, lo1, lo2, lo3, s2u(&skl[(pj * 16 + b_row) * LDK + kk * 16 + b_chk * 8]));
                u32 Bh0[2] = {h0, h1}, Bh1[2] = {h2, h3};
                u32 Bl0[2] = {lo0, lo1}, Bl1[2] = {lo2, lo3};
                mma_bf16(s[2*pj],   qh[kk], Bh0);
                mma_bf16(s[2*pj],   qh[kk], Bl0);
                mma_bf16(s[2*pj],   ql[kk], Bh0);
                mma_bf16(s[2*pj+1], qh[kk], Bh1);
                mma_bf16(s[2*pj+1], qh[kk], Bl1);
                mma_bf16(s[2*pj+1], ql[kk], Bh1);
            }
        }

        // ---- diagonal mask tile: banned iff col >= row (j0 - q0 == WIN) ----
        if (j0 == q0 + WIN) {
            const int r0 = wm + (lane >> 2);
            const int c0 = (lane & 3) * 2;
            #pragma unroll
            for (int ni = 0; ni < 8; ni++) {
                int col = ni * 8 + c0;
                if (col     >= r0)     s[ni][0] = -1e30f;
                if (col + 1 >= r0)     s[ni][1] = -1e30f;
                if (col     >= r0 + 8) s[ni][2] = -1e30f;
                if (col + 1 >= r0 + 8) s[ni][3] = -1e30f;
            }
        }

        // ---- online softmax (base 2; scale folded into Q) ----
        float mx0 = -1e30f, mx1 = -1e30f;
        #pragma unroll
        for (int ni = 0; ni < 8; ni++) {
            mx0 = fmaxf(mx0, fmaxf(s[ni][0], s[ni][1]));
            mx1 = fmaxf(mx1, fmaxf(s[ni][2], s[ni][3]));
        }
        mx0 = fmaxf(mx0, __shfl_xor_sync(0xffffffffu, mx0, 1));
        mx0 = fmaxf(mx0, __shfl_xor_sync(0xffffffffu, mx0, 2));
        mx1 = fmaxf(mx1, __shfl_xor_sync(0xffffffffu, mx1, 1));
        mx1 = fmaxf(mx1, __shfl_xor_sync(0xffffffffu, mx1, 2));
        float nm0 = fmaxf(m0, mx0), nm1 = fmaxf(m1, mx1);
        float cr0 = ex2_approx(m0 - nm0), cr1 = ex2_approx(m1 - nm1);
        m0 = nm0; m1 = nm1; l0 *= cr0; l1 *= cr1;
        #pragma unroll
        for (int ni = 0; ni < 8; ni++) {
            outf[ni][0] *= cr0; outf[ni][1] *= cr0;
            outf[ni][2] *= cr1; outf[ni][3] *= cr1;
        }
        #pragma unroll
        for (int ni = 0; ni < 8; ni++) {
            s[ni][0] = ex2_approx(s[ni][0] - m0);
            s[ni][1] = ex2_approx(s[ni][1] - m0);
            s[ni][2] = ex2_approx(s[ni][2] - m1);
            s[ni][3] = ex2_approx(s[ni][3] - m1);
            l0 += s[ni][0] + s[ni][1];
            l1 += s[ni][2] + s[ni][3];
        }

        cp_wait0();            // V ready
        __syncthreads();

        // ---- P V (3-pass split), V B-frags via ldmatrix.trans ----
        #pragma unroll
        for (int kk = 0; kk < 4; kk++) {
            float p00 = s[2*kk][0],   p01 = s[2*kk][1],   p02 = s[2*kk][2],   p03 = s[2*kk][3];
            float p10 = s[2*kk+1][0], p11 = s[2*kk+1][1], p12 = s[2*kk+1][2], p13 = s[2*kk+1][3];
            float h00 = bfr(p00), h01 = bfr(p01), h02 = bfr(p02), h03 = bfr(p03);
            float h10 = bfr(p10), h11 = bfr(p11), h12 = bfr(p12), h13 = bfr(p13);
            u32 ph[4] = { bf16x2(h01, h00), bf16x2(h03, h02), bf16x2(h11, h10), bf16x2(h13, h12) };
            u32 pl[4] = { bf16x2(p01 - h01, p00 - h00), bf16x2(p03 - h03, p02 - h02),
                          bf16x2(p11 - h11, p10 - h10), bf16x2(p13 - h13, p12 - h12) };
            #pragma unroll
            for (int pd = 0; pd < 4; pd++) {
                u32 v0, v1, v2, v3, w0, w1, w2, w3;
                ldsm4t(v0, v1, v2, v3, s2u(&svh[(kk * 16 + a_row) * LDK + pd * 16 + a_chk * 8]));
                ldsm4t(w0, w1, w2, w3, s2u(&svl[(kk * 16 + a_row) * LDK + pd * 16 + a_chk * 8]));
                u32 Vh0[2] = {v0, v1}, Vh1[2] = {v2, v3};
                u32 Vl0[2] = {w0, w1}, Vl1[2] = {w2, w3};
                mma_bf16(outf[2*pd],   ph, Vh0);
                mma_bf16(outf[2*pd],   ph, Vl0);
                mma_bf16(outf[2*pd],   pl, Vh0);
                mma_bf16(outf[2*pd+1], ph, Vh1);
                mma_bf16(outf[2*pd+1], ph, Vl1);
                mma_bf16(outf[2*pd+1], pl, Vh1);
            }
        }
        __syncthreads();   // smem safe to overwrite next iteration
    }

    // ---- finalize: l reduce across quad, divide, store ----
    l0 += __shfl_xor_sync(0xffffffffu, l0, 1);
    l0 += __shfl_xor_sync(0xffffffffu, l0, 2);
    l1 += __shfl_xor_sync(0xffffffffu, l1, 1);
    l1 += __shfl_xor_sync(0xffffffffu, l1, 2);
    const float i0 = 1.0f / l0, i1 = 1.0f / l1;

    const int r0 = q0 + wm + (lane >> 2);
    const int c0 = (lane & 3) * 2;
    #pragma unroll
    for (int nd = 0; nd < 8; nd++) {
        const int d = nd * 8 + c0;
        float* p0 = o_out + (size_t)(b * SS + r0) * DIMM + h * HDIM + d;
        p0[0] = outf[nd][0] * i0;
        p0[1] = outf[nd][1] * i0;
        float* p1 = o_out + (size_t)(b * SS + r0 + 8) * DIMM + h * HDIM + d;
        p1[0] = outf[nd][2] * i1;
        p1[1] = outf[nd][3] * i1;
    }
}

// ---------------- launch ----------------
extern "C" void kernel_launch(void* const* d_in, const int* in_sizes, int n_in,
                              void* d_out, int out_size)
{
    const float* x  = (const float*)d_in[0];
    const float* Wq = (const float*)d_in[1];
    const float* bq = (const float*)d_in[2];
    const float* Wk = (const float*)d_in[3];
    const float* bk = (const float*)d_in[4];
    const float* Wv = (const float*)d_in[5];
    const float* bv = (const float*)d_in[6];
    float* out = (float*)d_out;

    __nv_bfloat16 *xhi, *xlo, *whi, *wlo;
    cudaGetSymbolAddress((void**)&xhi, gx_hi);
    cudaGetSymbolAddress((void**)&xlo, gx_lo);
    cudaGetSymbolAddress((void**)&whi, gw_hi);
    cudaGetSymbolAddress((void**)&wlo, gw_lo);

    split_bf16<<<(NTOK * DIMM) / 1024, 256>>>(x, xhi, xlo, NTOK * DIMM);
    split_bf16<<<(DIMM * DIMM) / 1024, 256>>>(Wq, whi, wlo, DIMM * DIMM);
    split_bf16<<<(DIMM * DIMM) / 1024, 256>>>(Wk, whi + DIMM * DIMM, wlo + DIMM * DIMM, DIMM * DIMM);
    split_bf16<<<(DIMM * DIMM) / 1024, 256>>>(Wv, whi + 2 * DIMM * DIMM, wlo + 2 * DIMM * DIMM, DIMM * DIMM);

    dim3 ggrid(DIMM / 128, NTOK / 128, 3);
    qkv_gemm_tc<<<ggrid, 256>>>(bq, bk, bv);

    dim3 agrid(SS / 64, NHEADS, BB);   // 32 x 16 x 2 = 1024 blocks
    attn_mma<<<agrid, 128>>>(out);
}

// round 15
// speedup vs baseline: 1.0916x; 1.0367x over previous
#include <cuda_runtime.h>
#include <cuda_bf16.h>

// Problem constants
#define BB      2
#define SS      2048
#define DIMM    1024
#define NHEADS  16
#define HDIM    64
#define WIN     256
#define NTOK    (BB*SS)          // 4096

typedef unsigned long long u64;
typedef unsigned int u32;

// Scratch (device globals: allocation-free)
__device__ __nv_bfloat16 g_qhi[NTOK * DIMM];
__device__ __nv_bfloat16 g_qlo[NTOK * DIMM];
__device__ __nv_bfloat16 g_khi[NTOK * DIMM];
__device__ __nv_bfloat16 g_klo[NTOK * DIMM];
__device__ __nv_bfloat16 g_vhi[NTOK * DIMM];
__device__ __nv_bfloat16 g_vlo[NTOK * DIMM];
__device__ __nv_bfloat16 gx_hi[NTOK * DIMM];
__device__ __nv_bfloat16 gx_lo[NTOK * DIMM];
__device__ __nv_bfloat16 gw_hi[3 * DIMM * DIMM];
__device__ __nv_bfloat16 gw_lo[3 * DIMM * DIMM];

// ---------------- helpers ----------------
__device__ __forceinline__ float ex2_approx(float x) {
    float r; asm("ex2.approx.f32 %0, %1;" : "=f"(r) : "f"(x)); return r;
}
__device__ __forceinline__ void ldsm4(u32& r0, u32& r1, u32& r2, u32& r3, u32 addr) {
    asm volatile("ldmatrix.sync.aligned.m8n8.x4.shared.b16 {%0,%1,%2,%3}, [%4];"
                 : "=r"(r0), "=r"(r1), "=r"(r2), "=r"(r3) : "r"(addr));
}
__device__ __forceinline__ void ldsm4t(u32& r0, u32& r1, u32& r2, u32& r3, u32 addr) {
    asm volatile("ldmatrix.sync.aligned.m8n8.x4.trans.shared.b16 {%0,%1,%2,%3}, [%4];"
                 : "=r"(r0), "=r"(r1), "=r"(r2), "=r"(r3) : "r"(addr));
}
__device__ __forceinline__ void mma_bf16(float* c, const u32* a, const u32* b) {
    asm volatile("mma.sync.aligned.m16n8k16.row.col.f32.bf16.bf16.f32 "
                 "{%0,%1,%2,%3}, {%4,%5,%6,%7}, {%8,%9}, {%0,%1,%2,%3};"
                 : "+f"(c[0]), "+f"(c[1]), "+f"(c[2]), "+f"(c[3])
                 : "r"(a[0]), "r"(a[1]), "r"(a[2]), "r"(a[3]), "r"(b[0]), "r"(b[1]));
}
__device__ __forceinline__ void cp16(u32 saddr, const void* gaddr) {
    asm volatile("cp.async.cg.shared.global [%0], [%1], 16;" :: "r"(saddr), "l"(gaddr));
}
__device__ __forceinline__ void cp_commit() { asm volatile("cp.async.commit_group;"); }
__device__ __forceinline__ void cp_wait1()  { asm volatile("cp.async.wait_group 1;"); }
__device__ __forceinline__ void cp_wait0()  { asm volatile("cp.async.wait_group 0;"); }
__device__ __forceinline__ u32 s2u(const void* p) { return (u32)__cvta_generic_to_shared(p); }
__device__ __forceinline__ u32 bf16x2(float hi, float lo) {
    u32 d; asm("cvt.rn.bf16x2.f32 %0, %1, %2;" : "=r"(d) : "f"(hi), "f"(lo)); return d;
}
__device__ __forceinline__ float bfr(float x) {
    return __bfloat162float(__float2bfloat16(x));
}

// ---------------- Kernel 0: fp32 -> bf16 hi/lo split ----------------
__global__ void split_bf16(const float* __restrict__ src,
                           __nv_bfloat16* __restrict__ hi,
                           __nv_bfloat16* __restrict__ lo, int n)
{
    int i = (blockIdx.x * blockDim.x + threadIdx.x) * 4;
    if (i >= n) return;
    float4 v = *(const float4*)(src + i);
    union { __nv_bfloat16 b[4]; uint2 u; } H, L;
    H.b[0] = __float2bfloat16(v.x); L.b[0] = __float2bfloat16(v.x - __bfloat162float(H.b[0]));
    H.b[1] = __float2bfloat16(v.y); L.b[1] = __float2bfloat16(v.y - __bfloat162float(H.b[1]));
    H.b[2] = __float2bfloat16(v.z); L.b[2] = __float2bfloat16(v.z - __bfloat162float(H.b[2]));
    H.b[3] = __float2bfloat16(v.w); L.b[3] = __float2bfloat16(v.w - __bfloat162float(H.b[3]));
    *(uint2*)(hi + i) = H.u;
    *(uint2*)(lo + i) = L.u;
}

// ---------------- Kernel 1: QKV GEMM on tensor cores (bf16 split, BK=32) ----------------
// 128x128 tile, BK=32 (32 iterations), 2-stage cp.async, 8 warps, warp tile 32x64.
// Smem rows padded to 80B (conflict-free ldmatrix across 8 rows).
#define RSB      40                        // row stride in bf16 (80B)
#define G2_MATB  (128 * RSB * 2)           // 10240 bytes per matrix per stage
#define G2_STAGEB (4 * G2_MATB)            // 40960
#define G2_SMEM  (2 * G2_STAGEB)           // 81920

__global__ void __launch_bounds__(256) qkv_gemm_tc(
    const float* __restrict__ bq, const float* __restrict__ bk, const float* __restrict__ bv)
{
    extern __shared__ __align__(16) char dsm[];

    const int z = blockIdx.z;
    const __nv_bfloat16* Ahg = gx_hi;
    const __nv_bfloat16* Alg = gx_lo;
    const __nv_bfloat16* Bhg = gw_hi + (size_t)z * DIMM * DIMM;
    const __nv_bfloat16* Blg = gw_lo + (size_t)z * DIMM * DIMM;
    __nv_bfloat16* Chi = (z == 0) ? g_qhi : (z == 1) ? g_khi : g_vhi;
    __nv_bfloat16* Clo = (z == 0) ? g_qlo : (z == 1) ? g_klo : g_vlo;
    const float* bias = (z == 0) ? bq : (z == 1) ? bk : bv;
    const float scale = (z == 0) ? (0.125f * 1.4426950408889634f) : 1.0f;

    const int row0 = blockIdx.y * 128;
    const int col0 = blockIdx.x * 128;
    const int tid  = threadIdx.x;
    const int wid  = tid >> 5;
    const int lane = tid & 31;
    const int wm   = (wid & 3) * 32;
    const int wn   = (wid >> 2) * 64;

    float acc[2][8][4];
    #pragma unroll
    for (int mi = 0; mi < 2; mi++)
        #pragma unroll
        for (int ni = 0; ni < 8; ni++)
            #pragma unroll
            for (int e = 0; e < 4; e++) acc[mi][ni][e] = 0.0f;

    const int a_row = lane & 15, a_chk = lane >> 4;
    const int b_g = lane >> 3;
    const int b_row = (lane & 7) + ((b_g >> 1) << 3), b_chk = b_g & 1;

    // loader: 2048 16B chunks (4 matrices x 128 rows x 4 chunks), 8 per thread
    // c = tid + u*256: mat=c>>9, idx=c&511, row=idx>>2, cc=idx&3
    const int l_mat[8] = { (tid + 0*256) >> 9, (tid + 1*256) >> 9, (tid + 2*256) >> 9, (tid + 3*256) >> 9,
                           (tid + 4*256) >> 9, (tid + 5*256) >> 9, (tid + 6*256) >> 9, (tid + 7*256) >> 9 };
    (void)l_mat;

    #define G2_LOAD(stage, k0) do { \
        char* sb_ = dsm + (stage) * G2_STAGEB; \
        _Pragma("unroll") \
        for (int u_ = 0; u_ < 8; u_++) { \
            int c_ = tid + u_ * 256; \
            int mat_ = c_ >> 9, idx_ = c_ & 511; \
            int row_ = idx_ >> 2, cc_ = idx_ & 3; \
            const __nv_bfloat16* src_; size_t g_; \
            if (mat_ < 2) { src_ = (mat_ == 0) ? Ahg : Alg; g_ = (size_t)(row0 + row_) * DIMM + (k0) + cc_ * 8; } \
            else          { src_ = (mat_ == 2) ? Bhg : Blg; g_ = (size_t)(col0 + row_) * DIMM + (k0) + cc_ * 8; } \
            cp16(s2u(sb_ + mat_ * G2_MATB + row_ * 80 + cc_ * 16), src_ + g_); \
        } \
    } while (0)

    G2_LOAD(0, 0);
    cp_commit();

    #pragma unroll 1
    for (int it = 0; it < DIMM / 32; it++) {
        const int s = it & 1;
        if (it + 1 < DIMM / 32) {
            G2_LOAD(s ^ 1, (it + 1) * 32);
            cp_commit();
            cp_wait1();
        } else {
            cp_wait0();
        }
        __syncthreads();

        char* sb = dsm + s * G2_STAGEB;
        #pragma unroll
        for (int sub = 0; sub < 2; sub++) {
            const int cb = sub * 32;   // byte column base within the 64B row
            u32 ahi[2][4], alo[2][4], bhi[8][2], blo[8][2];
            #pragma unroll
            for (int mi = 0; mi < 2; mi++) {
                const int r = wm + mi * 16 + a_row;
                ldsm4(ahi[mi][0], ahi[mi][1], ahi[mi][2], ahi[mi][3],
                      s2u(sb + 0 * G2_MATB + r * 80 + cb + a_chk * 16));
                ldsm4(alo[mi][0], alo[mi][1], alo[mi][2], alo[mi][3],
                      s2u(sb + 1 * G2_MATB + r * 80 + cb + a_chk * 16));
            }
            #pragma unroll
            for (int p = 0; p < 4; p++) {
                const int r = wn + p * 16 + b_row;
                u32 r0, r1, r2, r3;
                ldsm4(r0, r1, r2, r3, s2u(sb + 2 * G2_MATB + r * 80 + cb + b_chk * 16));
                bhi[2*p][0] = r0; bhi[2*p][1] = r1; bhi[2*p+1][0] = r2; bhi[2*p+1][1] = r3;
                ldsm4(r0, r1, r2, r3, s2u(sb + 3 * G2_MATB + r * 80 + cb + b_chk * 16));
                blo[2*p][0] = r0; blo[2*p][1] = r1; blo[2*p+1][0] = r2; blo[2*p+1][1] = r3;
            }
            #pragma unroll
            for (int mi = 0; mi < 2; mi++)
                #pragma unroll
                for (int ni = 0; ni < 8; ni++) {
                    mma_bf16(acc[mi][ni], ahi[mi], bhi[ni]);
                    mma_bf16(acc[mi][ni], ahi[mi], blo[ni]);
                    mma_bf16(acc[mi][ni], alo[mi], bhi[ni]);
                }
        }
        __syncthreads();
    }

    // epilogue: bias + scale + bf16 hi/lo split stores
    const int crow = lane >> 2;
    const int ccol = (lane & 3) * 2;
    #pragma unroll
    for (int ni = 0; ni < 8; ni++) {
        const int n = col0 + wn + ni * 8 + ccol;
        const float b0 = bias[n], b1 = bias[n + 1];
        #pragma unroll
        for (int mi = 0; mi < 2; mi++) {
            #pragma unroll
            for (int half = 0; half < 2; half++) {
                const int m = row0 + wm + mi * 16 + crow + half * 8;
                float o0 = (acc[mi][ni][2*half]   + b0) * scale;
                float o1 = (acc[mi][ni][2*half+1] + b1) * scale;
                float h0 = bfr(o0), h1 = bfr(o1);
                size_t off = ((size_t)m * DIMM + n) >> 1;
                ((u32*)Chi)[off] = bf16x2(h1, h0);
                ((u32*)Clo)[off] = bf16x2(o1 - h1, o0 - h0);
            }
        }
    }
}

// ---------------- Kernel 2: flash attention on tensor cores (R12, unchanged) ----------------
#define LDK 72   // smem row stride in bf16 (144B) -> conflict-free ldmatrix

__global__ void __launch_bounds__(128) attn_mma(float* __restrict__ o_out)
{
    __shared__ __align__(16) __nv_bfloat16 skh[64 * LDK], skl[64 * LDK];
    __shared__ __align__(16) __nv_bfloat16 svh[64 * LDK], svl[64 * LDK];

    const int b  = blockIdx.z;
    const int h  = blockIdx.y;
    const int qt = (int)gridDim.x - 1 - (int)blockIdx.x;  // heavy tiles first
    const int q0 = qt * 64;
    const int tid = threadIdx.x;
    const int wid = tid >> 5;
    const int lane = tid & 31;
    const int wm = wid * 16;

    const int a_row = lane & 15, a_chk = lane >> 4;
    const int b_g = lane >> 3;
    const int b_row = (lane & 7) + ((b_g >> 1) << 3), b_chk = b_g & 1;

    // ---- load Q A-fragments (via smem staging in skh/skl) ----
    u32 qh[4][4], ql[4][4];
    {
        const __nv_bfloat16* gq  = g_qhi + (size_t)(b * SS + q0) * DIMM + h * HDIM;
        const __nv_bfloat16* gql = g_qlo + (size_t)(b * SS + q0) * DIMM + h * HDIM;
        #pragma unroll
        for (int u = 0; u < 4; u++) {
            int c = tid + u * 128;
            int row = c >> 3, cc = c & 7;
            cp16(s2u(&skh[row * LDK + cc * 8]), gq  + (size_t)row * DIMM + cc * 8);
            cp16(s2u(&skl[row * LDK + cc * 8]), gql + (size_t)row * DIMM + cc * 8);
        }
        cp_commit(); cp_wait0(); __syncthreads();
        #pragma unroll
        for (int kk = 0; kk < 4; kk++) {
            ldsm4(qh[kk][0], qh[kk][1], qh[kk][2], qh[kk][3],
                  s2u(&skh[(wm + a_row) * LDK + kk * 16 + a_chk * 8]));
            ldsm4(ql[kk][0], ql[kk][1], ql[kk][2], ql[kk][3],
                  s2u(&skl[(wm + a_row) * LDK + kk * 16 + a_chk * 8]));
        }
        __syncthreads();
    }

    float outf[8][4];
    #pragma unroll
    for (int ni = 0; ni < 8; ni++)
        #pragma unroll
        for (int e = 0; e < 4; e++) outf[ni][e] = 0.0f;
    float m0 = -1e30f, m1 = -1e30f, l0 = 0.0f, l1 = 0.0f;

    const int jend = min(SS, q0 + 63 + WIN);
    const __nv_bfloat16* Kh = g_khi + (size_t)(b * SS) * DIMM + h * HDIM;
    const __nv_bfloat16* Kl = g_klo + (size_t)(b * SS) * DIMM + h * HDIM;
    const __nv_bfloat16* Vh = g_vhi + (size_t)(b * SS) * DIMM + h * HDIM;
    const __nv_bfloat16* Vl = g_vlo + (size_t)(b * SS) * DIMM + h * HDIM;

    #pragma unroll 1
    for (int j0 = 0; j0 < jend; j0 += 64) {
        // group 1: K hi/lo
        #pragma unroll
        for (int u = 0; u < 8; u++) {
            int c = tid + u * 128;
            int arr = c >> 9, idx = c & 511;
            int row = idx >> 3, cc = idx & 7;
            size_t g = (size_t)(j0 + row) * DIMM + cc * 8;
            u32 d = (u32)(row * LDK + cc * 8);
            if (arr == 0) cp16(s2u(&skh[d]), Kh + g);
            else          cp16(s2u(&skl[d]), Kl + g);
        }
        cp_commit();
        // group 2: V hi/lo
        #pragma unroll
        for (int u = 8; u < 16; u++) {
            int c = tid + u * 128;
            int arr = (c >> 9) & 1, idx = c & 511;
            int row = idx >> 3, cc = idx & 7;
            size_t g = (size_t)(j0 + row) * DIMM + cc * 8;
            u32 d = (u32)(row * LDK + cc * 8);
            if (arr == 0) cp16(s2u(&svh[d]), Vh + g);
            else          cp16(s2u(&svl[d]), Vl + g);
        }
        cp_commit();

        cp_wait1();            // K ready; V still in flight
        __syncthreads();

        // S = Q K^T (3-pass split)
        float s[8][4];
        #pragma unroll
        for (int ni = 0; ni < 8; ni++)
            #pragma unroll
            for (int e = 0; e < 4; e++) s[ni][e] = 0.0f;

        #pragma unroll
        for (int pj = 0; pj < 4; pj++) {
            #pragma unroll
            for (int kk = 0; kk < 4; kk++) {
                u32 h0, h1, h2, h3, lo0, lo1, lo2, lo3;
                ldsm4(h0, h1, h2, h3,     s2u(&skh[(pj * 16 + b_row) * LDK + kk * 16 + b_chk * 8]));
                ldsm4(lo0, lo1, lo2, lo3, s2u(&skl[(pj * 16 + b_row) * LDK + kk * 16 + b_chk * 8]));
                u32 Bh0[2] = {h0, h1}, Bh1[2] = {h2, h3};
                u32 Bl0[2] = {lo0, lo1}, Bl1[2] = {lo2, lo3};
                mma_bf16(s[2*pj],   qh[kk], Bh0);
                mma_bf16(s[2*pj],   qh[kk], Bl0);
                mma_bf16(s[2*pj],   ql[kk], Bh0);
                mma_bf16(s[2*pj+1], qh[kk], Bh1);
                mma_bf16(s[2*pj+1], qh[kk], Bl1);
                mma_bf16(s[2*pj+1], ql[kk], Bh1);
            }
        }

        // diagonal mask tile: banned iff col >= row (j0 - q0 == WIN)
        if (j0 == q0 + WIN) {
            const int r0 = wm + (lane >> 2);
            const int c0 = (lane & 3) * 2;
            #pragma unroll
            for (int ni = 0; ni < 8; ni++) {
                int col = ni * 8 + c0;
                if (col     >= r0)     s[ni][0] = -1e30f;
                if (col + 1 >= r0)     s[ni][1] = -1e30f;
                if (col     >= r0 + 8) s[ni][2] = -1e30f;
                if (col + 1 >= r0 + 8) s[ni][3] = -1e30f;
            }
        }

        // online softmax (base 2; scale folded into Q)
        float mx0 = -1e30f, mx1 = -1e30f;
        #pragma unroll
        for (int ni = 0; ni < 8; ni++) {
            mx0 = fmaxf(mx0, fmaxf(s[ni][0], s[ni][1]));
            mx1 = fmaxf(mx1, fmaxf(s[ni][2], s[ni][3]));
        }
        mx0 = fmaxf(mx0, __shfl_xor_sync(0xffffffffu, mx0, 1));
        mx0 = fmaxf(mx0, __shfl_xor_sync(0xffffffffu, mx0, 2));
        mx1 = fmaxf(mx1, __shfl_xor_sync(0xffffffffu, mx1, 1));
        mx1 = fmaxf(mx1, __shfl_xor_sync(0xffffffffu, mx1, 2));
        float nm0 = fmaxf(m0, mx0), nm1 = fmaxf(m1, mx1);
        float cr0 = ex2_approx(m0 - nm0), cr1 = ex2_approx(m1 - nm1);
        m0 = nm0; m1 = nm1; l0 *= cr0; l1 *= cr1;
        #pragma unroll
        for (int ni = 0; ni < 8; ni++) {
            outf[ni][0] *= cr0; outf[ni][1] *= cr0;
            outf[ni][2] *= cr1; outf[ni][3] *= cr1;
        }
        #pragma unroll
        for (int ni = 0; ni < 8; ni++) {
            s[ni][0] = ex2_approx(s[ni][0] - m0);
            s[ni][1] = ex2_approx(s[ni][1] - m0);
            s[ni][2] = ex2_approx(s[ni][2] - m1);
            s[ni][3] = ex2_approx(s[ni][3] - m1);
            l0 += s[ni][0] + s[ni][1];
            l1 += s[ni][2] + s[ni][3];
        }

        cp_wait0();            // V ready
        __syncthreads();

        // P V (3-pass split), V B-frags via ldmatrix.trans
        #pragma unroll
        for (int kk = 0; kk < 4; kk++) {
            float p00 = s[2*kk][0],   p01 = s[2*kk][1],   p02 = s[2*kk][2],   p03 = s[2*kk][3];
            float p10 = s[2*kk+1][0], p11 = s[2*kk+1][1], p12 = s[2*kk+1][2], p13 = s[2*kk+1][3];
            float h00 = bfr(p00), h01 = bfr(p01), h02 = bfr(p02), h03 = bfr(p03);
            float h10 = bfr(p10), h11 = bfr(p11), h12 = bfr(p12), h13 = bfr(p13);
            u32 ph[4] = { bf16x2(h01, h00), bf16x2(h03, h02), bf16x2(h11, h10), bf16x2(h13, h12) };
            u32 pl[4] = { bf16x2(p01 - h01, p00 - h00), bf16x2(p03 - h03, p02 - h02),
                          bf16x2(p11 - h11, p10 - h10), bf16x2(p13 - h13, p12 - h12) };
            #pragma unroll
            for (int pd = 0; pd < 4; pd++) {
                u32 v0, v1, v2, v3, w0, w1, w2, w3;
                ldsm4t(v0, v1, v2, v3, s2u(&svh[(kk * 16 + a_row) * LDK + pd * 16 + a_chk * 8]));
                ldsm4t(w0, w1, w2, w3, s2u(&svl[(kk * 16 + a_row) * LDK + pd * 16 + a_chk * 8]));
                u32 Vh0[2] = {v0, v1}, Vh1[2] = {v2, v3};
                u32 Vl0[2] = {w0, w1}, Vl1[2] = {w2, w3};
                mma_bf16(outf[2*pd],   ph, Vh0);
                mma_bf16(outf[2*pd],   ph, Vl0);
                mma_bf16(outf[2*pd],   pl, Vh0);
                mma_bf16(outf[2*pd+1], ph, Vh1);
                mma_bf16(outf[2*pd+1], ph, Vl1);
                mma_bf16(outf[2*pd+1], pl, Vh1);
            }
        }
        __syncthreads();
    }

    // finalize
    l0 += __shfl_xor_sync(0xffffffffu, l0, 1);
    l0 += __shfl_xor_sync(0xffffffffu, l0, 2);
    l1 += __shfl_xor_sync(0xffffffffu, l1, 1);
    l1 += __shfl_xor_sync(0xffffffffu, l1, 2);
    const float i0 = 1.0f / l0, i1 = 1.0f / l1;

    const int r0 = q0 + wm + (lane >> 2);
    const int c0 = (lane & 3) * 2;
    #pragma unroll
    for (int nd = 0; nd < 8; nd++) {
        const int d = nd * 8 + c0;
        float* p0 = o_out + (size_t)(b * SS + r0) * DIMM + h * HDIM + d;
        p0[0] = outf[nd][0] * i0;
        p0[1] = outf[nd][1] * i0;
        float* p1 = o_out + (size_t)(b * SS + r0 + 8) * DIMM + h * HDIM + d;
        p1[0] = outf[nd][2] * i1;
        p1[1] = outf[nd][3] * i1;
    }
}

// ---------------- launch ----------------
extern "C" void kernel_launch(void* const* d_in, const int* in_sizes, int n_in,
                              void* d_out, int out_size)
{
    const float* x  = (const float*)d_in[0];
    const float* Wq = (const float*)d_in[1];
    const float* bq = (const float*)d_in[2];
    const float* Wk = (const float*)d_in[3];
    const float* bk = (const float*)d_in[4];
    const float* Wv = (const float*)d_in[5];
    const float* bv = (const float*)d_in[6];
    float* out = (float*)d_out;

    __nv_bfloat16 *xhi, *xlo, *whi, *wlo;
    cudaGetSymbolAddress((void**)&xhi, gx_hi);
    cudaGetSymbolAddress((void**)&xlo, gx_lo);
    cudaGetSymbolAddress((void**)&whi, gw_hi);
    cudaGetSymbolAddress((void**)&wlo, gw_lo);

    split_bf16<<<(NTOK * DIMM) / 1024, 256>>>(x, xhi, xlo, NTOK * DIMM);
    split_bf16<<<(DIMM * DIMM) / 1024, 256>>>(Wq, whi, wlo, DIMM * DIMM);
    split_bf16<<<(DIMM * DIMM) / 1024, 256>>>(Wk, whi + DIMM * DIMM, wlo + DIMM * DIMM, DIMM * DIMM);
    split_bf16<<<(DIMM * DIMM) / 1024, 256>>>(Wv, whi + 2 * DIMM * DIMM, wlo + 2 * DIMM * DIMM, DIMM * DIMM);

    // BK=32 mma.sync GEMM (idempotent attribute set; no static guards)
    cudaFuncSetAttribute(qkv_gemm_tc, cudaFuncAttributeMaxDynamicSharedMemorySize, G2_SMEM);
    dim3 ggrid(DIMM / 128, NTOK / 128, 3);
    qkv_gemm_tc<<<ggrid, 256, G2_SMEM>>>(bq, bk, bv);

    dim3 agrid(SS / 64, NHEADS, BB);   // 32 x 16 x 2 = 1024 blocks
    attn_mma<<<agrid, 128>>>(out);
}